// round 10
// baseline (speedup 1.0000x reference)
#include <cuda_runtime.h>
#include <cuda_bf16.h>

// Problem constants (match reference)
#define WPIX 512.0f
#define HPIX 512.0f
#define S_MIN (1.0f / 30.0f)
#define S_MAX (1.0f / 0.75f)
#define MU_BORDER 1.05f
#define PI_APPROX 3.1416f

#define MAX_N 512
#define MAX_B 65536
#define TILE_PX 16.0f
#define TILES_X 32
#define TILES_Y 32
#define NUM_TILES (TILES_X * TILES_Y)
#define PRE_BLOCKS 16
#define G_PER_BLOCK 32        // 512 / 16
#define CAP 256               // bucket capacity per tile (mean load = 32)

// ---- per-gaussian precomputed data ----
__device__ float4 g_ga[MAX_N];          // (gmx, gmy, Sx, Sy), centered px coords
__device__ float4 g_gb[MAX_N];          // (cos a, sin a, sigmoid(op), 0)
__device__ float4 g_sh[MAX_N * 7];      // repacked 27 SH coeffs + pad
__device__ float4 g_bbox[MAX_N];        // (xmin, xmax, ymin, ymax), raw px

// ---- direct ray buckets ----
__device__ int    g_hist[NUM_TILES];    // .bss zero; re-zeroed by splat each call
__device__ float2 g_bxy[NUM_TILES * CAP];
__device__ int    g_bid[NUM_TILES * CAP];
// overflow (correctness fallback; empty for benchmark inputs)
__device__ int    g_ovf_cnt;
__device__ float2 g_ovf_xy[MAX_B];
__device__ int    g_ovf_id[MAX_B];

__device__ __forceinline__ int tile_of(float xr, float yr) {
    int tx = min(TILES_X - 1, max(0, (int)(xr * (1.0f / TILE_PX))));
    int ty = min(TILES_Y - 1, max(0, (int)(yr * (1.0f / TILE_PX))));
    return ty * TILES_X + tx;
}

// shared per-pair math (identical FP sequence everywhere)
__device__ __forceinline__ void splat_accum(
    float px, float py, float4 ga, const float4* __restrict__ gbp,
    const float4* __restrict__ shp,
    float& sumR, float& sumG, float& sumB)
{
    float vx = px - ga.x;
    float vy = py - ga.y;
    float svx = vx * ga.z;
    float svy = vy * ga.w;
    float d2 = fmaf(svx, svx, svy * svy);
    if (d2 < 25.0f) {
        float4 gb = *gbp;
        float4 q0 = shp[0], q1 = shp[1], q2 = shp[2], q3 = shp[3];
        float4 q4 = shp[4], q5 = shp[5], q6 = shp[6];

        float c = gb.x, sa = gb.y;
        float w = __expf(-d2) * gb.z;

        float rvx = c * vx - sa * vy;
        float rvy = fmaf(sa, vx, c * vy);
        float rn = rsqrtf(fmaf(rvx, rvx, fmaf(rvy, rvy, 1e-20f)));
        float s1 = rvx * rn;   // sin(theta)
        float c1 = rvy * rn;   // cos(theta)
        float s2 = 2.0f * s1 * c1;
        float c2 = fmaf(c1, c1, -s1 * s1);
        float s3 = fmaf(s1, c2, c1 * s2);
        float c3 = fmaf(c1, c2, -s1 * s2);
        float s4 = 2.0f * s2 * c2;
        float c4 = fmaf(c2, c2, -s2 * s2);

        float aR = q0.x;
        aR = fmaf(s1, q0.w, aR); aR = fmaf(c1, q1.z, aR);
        aR = fmaf(s2, q2.y, aR); aR = fmaf(c2, q3.x, aR);
        aR = fmaf(s3, q3.w, aR); aR = fmaf(c3, q4.z, aR);
        aR = fmaf(s4, q5.y, aR); aR = fmaf(c4, q6.x, aR);
        float aG = q0.y;
        aG = fmaf(s1, q1.x, aG); aG = fmaf(c1, q1.w, aG);
        aG = fmaf(s2, q2.z, aG); aG = fmaf(c2, q3.y, aG);
        aG = fmaf(s3, q4.x, aG); aG = fmaf(c3, q4.w, aG);
        aG = fmaf(s4, q5.z, aG); aG = fmaf(c4, q6.y, aG);
        float aB = q0.z;
        aB = fmaf(s1, q1.y, aB); aB = fmaf(c1, q2.x, aB);
        aB = fmaf(s2, q2.w, aB); aB = fmaf(c2, q3.z, aB);
        aB = fmaf(s3, q4.y, aB); aB = fmaf(c3, q5.x, aB);
        aB = fmaf(s4, q5.w, aB); aB = fmaf(c4, q6.z, aB);

        float rR = __fdividef(1.0f, 1.0f + __expf(-aR));
        float rG = __fdividef(1.0f, 1.0f + __expf(-aG));
        float rB = __fdividef(1.0f, 1.0f + __expf(-aB));
        sumR = fmaf(w, rR, sumR);
        sumG = fmaf(w, rG, sumG);
        sumB = fmaf(w, rB, sumB);
    }
}

// ============================================================================
// K1: blocks [0, binBlocks): ray binning -> direct bucket scatter (2 rays/thr)
//     blocks [binBlocks, binBlocks+PRE_BLOCKS): per-gaussian precompute
// 256 threads/block.
// ============================================================================
__global__ __launch_bounds__(256)
void prep_kernel(const float* __restrict__ x,
                 const float* __restrict__ rgbsh,
                 const float* __restrict__ opacity,
                 const float* __restrict__ mu,
                 const float* __restrict__ scale,
                 const float* __restrict__ angle,
                 int B, int N, int binBlocks) {
    int bid = blockIdx.x;
    int tid = threadIdx.x;

    if (bid < binBlocks) {
        const float4* x4 = (const float4*)x;
        int f = bid * 256 + tid;            // float4 index = rays 2f, 2f+1
        if (2 * f < B) {
            float4 v = x4[f];
#pragma unroll
            for (int j = 0; j < 2; ++j) {
                int r = 2 * f + j;
                if (r < B) {
                    float xr = (j == 0) ? v.x : v.z;
                    float yr = (j == 0) ? v.y : v.w;
                    int t = tile_of(xr, yr);
                    int pos = atomicAdd(&g_hist[t], 1);
                    if (pos < CAP) {
                        g_bxy[t * CAP + pos] = make_float2(xr, yr);
                        g_bid[t * CAP + pos] = r;
                    } else {
                        int o = atomicAdd(&g_ovf_cnt, 1);
                        g_ovf_xy[o] = make_float2(xr, yr);
                        g_ovf_id[o] = r;
                    }
                }
            }
        }
    } else {
        int g0 = (bid - binBlocks) * G_PER_BLOCK;
        if (tid < G_PER_BLOCK) {
            int n = g0 + tid;
            if (n < N) {
                float gmx = tanhf(mu[2 * n + 0]) * (MU_BORDER * WPIX * 0.5f);
                float gmy = tanhf(mu[2 * n + 1]) * (MU_BORDER * HPIX * 0.5f);
                float sx = fminf(fmaxf(scale[2 * n + 0], 0.0f), 1.0f) * (S_MAX - S_MIN) + S_MIN;
                float sy = fminf(fmaxf(scale[2 * n + 1], 0.0f), 1.0f) * (S_MAX - S_MIN) + S_MIN;
                g_ga[n] = make_float4(gmx, gmy, sx, sy);

                float hx = __fdividef(5.0f, sx) + 0.05f;   // fp-rounding margin
                float hy = __fdividef(5.0f, sy) + 0.05f;
                float cx = gmx + WPIX * 0.5f;
                float cy = gmy + HPIX * 0.5f;
                g_bbox[n] = make_float4(cx - hx, cx + hx, cy - hy, cy + hy);

                float alpha = tanhf(angle[n]) * PI_APPROX;
                float c, s;
                sincosf(alpha, &s, &c);
                float op = 1.0f / (1.0f + expf(-opacity[n]));
                g_gb[n] = make_float4(c, s, op, 0.0f);
            }
        } else {
            // SH repack: 224 tasks = 32 gaussians x 7 slots
            int task = tid - G_PER_BLOCK;
            int sl = task / 7;
            int j = task - sl * 7;
            int n = g0 + sl;
            if (n < N) {
                int c0 = 4 * j;
                float v0 = rgbsh[n * 27 + c0];
                float v1 = (c0 + 1 < 27) ? rgbsh[n * 27 + c0 + 1] : 0.0f;
                float v2 = (c0 + 2 < 27) ? rgbsh[n * 27 + c0 + 2] : 0.0f;
                float v3 = (c0 + 3 < 27) ? rgbsh[n * 27 + c0 + 3] : 0.0f;
                g_sh[n * 7 + j] = make_float4(v0, v1, v2, v3);
            }
        }
    }
}

// ============================================================================
// K2: splat — WARP per tile (32-thread blocks, no __syncthreads).
//     Inline list build via ballots; gaussian data read as warp-uniform
//     broadcast LDGs (L1-resident after warmup).
//     Block NUM_TILES: overflow fallback (empty in practice).
// ============================================================================
__global__ __launch_bounds__(32)
void splat_kernel(float* __restrict__ out, int B, int N) {
    __shared__ int s_list[MAX_N];

    int t = blockIdx.x;
    int lane = threadIdx.x;

    if (t == NUM_TILES) {
        int nOvf = g_ovf_cnt;
        __syncwarp();
        if (lane == 0) g_ovf_cnt = 0;
        int cap = (nOvf < MAX_B) ? nOvf : MAX_B;
        for (int i = lane; i < cap; i += 32) {
            float2 xy = g_ovf_xy[i];
            int ray = g_ovf_id[i];
            float px = xy.x - (WPIX * 0.5f);
            float py = xy.y - (HPIX * 0.5f);
            float sumR = 0.0f, sumG = 0.0f, sumB = 0.0f;
            for (int n = 0; n < N; ++n)
                splat_accum(px, py, g_ga[n], &g_gb[n], &g_sh[n * 7], sumR, sumG, sumB);
            out[3 * ray + 0] = sumR;
            out[3 * ray + 1] = sumG;
            out[3 * ray + 2] = sumB;
        }
        return;
    }

    int hist = g_hist[t];
    int rayCount = (hist < CAP) ? hist : CAP;
    if (lane == 0) g_hist[t] = 0;          // replay idempotence
    if (rayCount == 0) return;

    // ---- inline list build: 16 ballot rounds, loads batched for MLP ----
    int tx = t & (TILES_X - 1);
    int ty = t >> 5;
    float x0 = tx * TILE_PX, x1 = x0 + TILE_PX;
    float y0 = ty * TILE_PX, y1 = y0 + TILE_PX;

    int nChunks = (N + 31) >> 5;           // 16 for N=512
    unsigned ok_bits[16];
#pragma unroll
    for (int c = 0; c < 16; ++c) {
        bool ok = false;
        int g = c * 32 + lane;
        if (c < nChunks && g < N) {
            float4 bb = g_bbox[g];         // 16 independent LDG.128 (MLP)
            ok = (bb.x <= x1) && (bb.y >= x0) && (bb.z <= y1) && (bb.w >= y0);
        }
        ok_bits[c] = ok ? 1u : 0u;
    }
    int cnt = 0;
#pragma unroll
    for (int c = 0; c < 16; ++c) {
        unsigned m = __ballot_sync(0xFFFFFFFFu, ok_bits[c]);
        if (ok_bits[c]) {
            int off = __popc(m & ((1u << lane) - 1u));
            s_list[cnt + off] = c * 32 + lane;
        }
        cnt += __popc(m);
    }
    __syncwarp();

    int bbase = t * CAP;
    for (int r0 = 0; r0 < rayCount; r0 += 32) {
        int myIdx = r0 + lane;
        bool active = myIdx < rayCount;
        int ray = 0;
        float px = 0.0f, py = 0.0f;
        if (active) {
            float2 xy = g_bxy[bbase + myIdx];   // coalesced
            ray = g_bid[bbase + myIdx];
            px = xy.x - (WPIX * 0.5f);
            py = xy.y - (HPIX * 0.5f);
        }
        float sumR = 0.0f, sumG = 0.0f, sumB = 0.0f;

        for (int i = 0; i < cnt; ++i) {
            int n = s_list[i];                  // warp-uniform -> broadcasts below
            float4 ga = g_ga[n];
            if (active)
                splat_accum(px, py, ga, &g_gb[n], &g_sh[n * 7], sumR, sumG, sumB);
        }

        if (active) {
            out[3 * ray + 0] = sumR;
            out[3 * ray + 1] = sumG;
            out[3 * ray + 2] = sumB;
        }
    }
}

extern "C" void kernel_launch(void* const* d_in, const int* in_sizes, int n_in,
                              void* d_out, int out_size) {
    // metadata order: x, rgbsh, opacity, mu, scale, angle
    const float* x       = (const float*)d_in[0];
    const float* rgbsh   = (const float*)d_in[1];
    const float* opacity = (const float*)d_in[2];
    const float* mu      = (const float*)d_in[3];
    const float* scale   = (const float*)d_in[4];
    const float* angle   = (const float*)d_in[5];
    float* out = (float*)d_out;

    int B = in_sizes[0] / 2;
    int N = in_sizes[2];
    if (N > MAX_N) N = MAX_N;

    // binning: 2 rays per thread (one float4), 512 rays per 256-thread block
    int binBlocks = (B + 511) / 512;
    prep_kernel<<<binBlocks + PRE_BLOCKS, 256>>>(x, rgbsh, opacity, mu, scale, angle, B, N, binBlocks);

    splat_kernel<<<NUM_TILES + 1, 32>>>(out, B, N);
}

// round 11
// speedup vs baseline: 1.4663x; 1.4663x over previous
#include <cuda_runtime.h>
#include <cuda_bf16.h>

// Problem constants (match reference)
#define WPIX 512.0f
#define HPIX 512.0f
#define S_MIN (1.0f / 30.0f)
#define S_MAX (1.0f / 0.75f)
#define MU_BORDER 1.05f
#define PI_APPROX 3.1416f

#define MAX_N 512
#define MAX_B 65536
#define TILE_PX 16.0f
#define TILES_X 32
#define TILES_Y 32
#define NUM_TILES (TILES_X * TILES_Y)
#define PRE_BLOCKS 16
#define G_PER_BLOCK 32        // 512 / 16
#define CAP 256               // bucket capacity per tile (mean load = 32)
#define MASK_WORDS 16         // 512 bits per tile

// ---- per-gaussian precomputed data ----
__device__ float4 g_ga[MAX_N];          // (gmx, gmy, Sx, Sy), centered px coords
__device__ float4 g_gb[MAX_N];          // (cos a, sin a, sigmoid(op), 0)
__device__ float4 g_sh[MAX_N * 7];      // repacked 27 SH coeffs + pad

// ---- tile -> gaussian candidacy bitmasks (atomicOr = order-independent) ----
__device__ unsigned g_mask[NUM_TILES * MASK_WORDS];  // .bss zero; splat re-zeroes

// ---- direct ray buckets ----
__device__ int    g_hist[NUM_TILES];    // .bss zero; re-zeroed by splat each call
__device__ float2 g_bxy[NUM_TILES * CAP];
__device__ int    g_bid[NUM_TILES * CAP];
// overflow (correctness fallback; empty for benchmark inputs)
__device__ int    g_ovf_cnt;
__device__ float2 g_ovf_xy[MAX_B];
__device__ int    g_ovf_id[MAX_B];

__device__ __forceinline__ int tile_of(float xr, float yr) {
    int tx = min(TILES_X - 1, max(0, (int)(xr * (1.0f / TILE_PX))));
    int ty = min(TILES_Y - 1, max(0, (int)(yr * (1.0f / TILE_PX))));
    return ty * TILES_X + tx;
}

// shared per-pair math (identical FP sequence everywhere)
__device__ __forceinline__ void splat_accum(
    float px, float py, float4 ga, const float4* __restrict__ gbp,
    const float4* __restrict__ shp,
    float& sumR, float& sumG, float& sumB)
{
    float vx = px - ga.x;
    float vy = py - ga.y;
    float svx = vx * ga.z;
    float svy = vy * ga.w;
    float d2 = fmaf(svx, svx, svy * svy);
    if (d2 < 25.0f) {
        float4 gb = *gbp;
        float4 q0 = shp[0], q1 = shp[1], q2 = shp[2], q3 = shp[3];
        float4 q4 = shp[4], q5 = shp[5], q6 = shp[6];

        float c = gb.x, sa = gb.y;
        float w = __expf(-d2) * gb.z;

        float rvx = c * vx - sa * vy;
        float rvy = fmaf(sa, vx, c * vy);
        float rn = rsqrtf(fmaf(rvx, rvx, fmaf(rvy, rvy, 1e-20f)));
        float s1 = rvx * rn;   // sin(theta)
        float c1 = rvy * rn;   // cos(theta)
        float s2 = 2.0f * s1 * c1;
        float c2 = fmaf(c1, c1, -s1 * s1);
        float s3 = fmaf(s1, c2, c1 * s2);
        float c3 = fmaf(c1, c2, -s1 * s2);
        float s4 = 2.0f * s2 * c2;
        float c4 = fmaf(c2, c2, -s2 * s2);

        float aR = q0.x;
        aR = fmaf(s1, q0.w, aR); aR = fmaf(c1, q1.z, aR);
        aR = fmaf(s2, q2.y, aR); aR = fmaf(c2, q3.x, aR);
        aR = fmaf(s3, q3.w, aR); aR = fmaf(c3, q4.z, aR);
        aR = fmaf(s4, q5.y, aR); aR = fmaf(c4, q6.x, aR);
        float aG = q0.y;
        aG = fmaf(s1, q1.x, aG); aG = fmaf(c1, q1.w, aG);
        aG = fmaf(s2, q2.z, aG); aG = fmaf(c2, q3.y, aG);
        aG = fmaf(s3, q4.x, aG); aG = fmaf(c3, q4.w, aG);
        aG = fmaf(s4, q5.z, aG); aG = fmaf(c4, q6.y, aG);
        float aB = q0.z;
        aB = fmaf(s1, q1.y, aB); aB = fmaf(c1, q2.x, aB);
        aB = fmaf(s2, q2.w, aB); aB = fmaf(c2, q3.z, aB);
        aB = fmaf(s3, q4.y, aB); aB = fmaf(c3, q5.x, aB);
        aB = fmaf(s4, q5.w, aB); aB = fmaf(c4, q6.z, aB);

        float rR = __fdividef(1.0f, 1.0f + __expf(-aR));
        float rG = __fdividef(1.0f, 1.0f + __expf(-aG));
        float rB = __fdividef(1.0f, 1.0f + __expf(-aB));
        sumR = fmaf(w, rR, sumR);
        sumG = fmaf(w, rG, sumG);
        sumB = fmaf(w, rB, sumB);
    }
}

// ============================================================================
// K1: blocks [0, binBlocks): ray binning -> direct bucket scatter (2 rays/thr)
//     blocks [binBlocks, binBlocks+PRE_BLOCKS): per-gaussian precompute +
//       bitmask scatter (atomicOr, order-independent -> deterministic)
// 256 threads/block.
// ============================================================================
__global__ __launch_bounds__(256)
void prep_kernel(const float* __restrict__ x,
                 const float* __restrict__ rgbsh,
                 const float* __restrict__ opacity,
                 const float* __restrict__ mu,
                 const float* __restrict__ scale,
                 const float* __restrict__ angle,
                 int B, int N, int binBlocks) {
    int bid = blockIdx.x;
    int tid = threadIdx.x;

    if (bid < binBlocks) {
        const float4* x4 = (const float4*)x;
        int f = bid * 256 + tid;            // float4 index = rays 2f, 2f+1
        if (2 * f < B) {
            float4 v = x4[f];
#pragma unroll
            for (int j = 0; j < 2; ++j) {
                int r = 2 * f + j;
                if (r < B) {
                    float xr = (j == 0) ? v.x : v.z;
                    float yr = (j == 0) ? v.y : v.w;
                    int t = tile_of(xr, yr);
                    int pos = atomicAdd(&g_hist[t], 1);
                    if (pos < CAP) {
                        g_bxy[t * CAP + pos] = make_float2(xr, yr);
                        g_bid[t * CAP + pos] = r;
                    } else {
                        int o = atomicAdd(&g_ovf_cnt, 1);
                        g_ovf_xy[o] = make_float2(xr, yr);
                        g_ovf_id[o] = r;
                    }
                }
            }
        }
    } else {
        int g0 = (bid - binBlocks) * G_PER_BLOCK;
        if (tid < G_PER_BLOCK) {
            int n = g0 + tid;
            if (n < N) {
                float gmx = tanhf(mu[2 * n + 0]) * (MU_BORDER * WPIX * 0.5f);
                float gmy = tanhf(mu[2 * n + 1]) * (MU_BORDER * HPIX * 0.5f);
                float sx = fminf(fmaxf(scale[2 * n + 0], 0.0f), 1.0f) * (S_MAX - S_MIN) + S_MIN;
                float sy = fminf(fmaxf(scale[2 * n + 1], 0.0f), 1.0f) * (S_MAX - S_MIN) + S_MIN;
                g_ga[n] = make_float4(gmx, gmy, sx, sy);

                float alpha = tanhf(angle[n]) * PI_APPROX;
                float c, s;
                sincosf(alpha, &s, &c);
                float op = 1.0f / (1.0f + expf(-opacity[n]));
                g_gb[n] = make_float4(c, s, op, 0.0f);

                // conservative bbox of valid ellipse, raw pixel coords
                float hx = __fdividef(5.0f, sx) + 0.05f;
                float hy = __fdividef(5.0f, sy) + 0.05f;
                float cx = gmx + WPIX * 0.5f;
                float cy = gmy + HPIX * 0.5f;
                float xmin = cx - hx, xmax = cx + hx;
                float ymin = cy - hy, ymax = cy + hy;

                // tile rect overlapping bbox (closed-interval semantics, conservative)
                int tx0 = max(0, (int)ceilf(xmin * (1.0f / TILE_PX)) - 1);
                int tx1 = min(TILES_X - 1, (int)floorf(xmax * (1.0f / TILE_PX)));
                int ty0 = max(0, (int)ceilf(ymin * (1.0f / TILE_PX)) - 1);
                int ty1 = min(TILES_Y - 1, (int)floorf(ymax * (1.0f / TILE_PX)));

                unsigned bit = 1u << (n & 31);
                int word = n >> 5;
                for (int ty = ty0; ty <= ty1; ++ty)
                    for (int tx = tx0; tx <= tx1; ++tx)
                        atomicOr(&g_mask[(ty * TILES_X + tx) * MASK_WORDS + word], bit);
            }
        } else {
            // SH repack: 224 tasks = 32 gaussians x 7 slots
            int task = tid - G_PER_BLOCK;
            int sl = task / 7;
            int j = task - sl * 7;
            int n = g0 + sl;
            if (n < N) {
                int c0 = 4 * j;
                float v0 = rgbsh[n * 27 + c0];
                float v1 = (c0 + 1 < 27) ? rgbsh[n * 27 + c0 + 1] : 0.0f;
                float v2 = (c0 + 2 < 27) ? rgbsh[n * 27 + c0 + 2] : 0.0f;
                float v3 = (c0 + 3 < 27) ? rgbsh[n * 27 + c0 + 3] : 0.0f;
                g_sh[n * 7 + j] = make_float4(v0, v1, v2, v3);
            }
        }
    }
}

// ============================================================================
// K2: splat — 128 threads per tile; warp w owns mask words 4w..4w+3
// (gaussians 128w..128w+127). Partial RGB per warp, fixed-order smem reduce.
// Block NUM_TILES: overflow fallback (empty in practice).
// ============================================================================
__global__ __launch_bounds__(128)
void splat_kernel(float* __restrict__ out, int B, int N) {
    int t = blockIdx.x;
    int tid = threadIdx.x;
    int warp = tid >> 5;
    int lane = tid & 31;

    if (t == NUM_TILES) {
        int nOvf = g_ovf_cnt;
        __syncthreads();
        if (tid == 0) g_ovf_cnt = 0;
        int cap = (nOvf < MAX_B) ? nOvf : MAX_B;
        for (int i = tid; i < cap; i += 128) {
            float2 xy = g_ovf_xy[i];
            int ray = g_ovf_id[i];
            float px = xy.x - (WPIX * 0.5f);
            float py = xy.y - (HPIX * 0.5f);
            float sumR = 0.0f, sumG = 0.0f, sumB = 0.0f;
            for (int n = 0; n < N; ++n)
                splat_accum(px, py, g_ga[n], &g_gb[n], &g_sh[n * 7], sumR, sumG, sumB);
            out[3 * ray + 0] = sumR;
            out[3 * ray + 1] = sumG;
            out[3 * ray + 2] = sumB;
        }
        return;
    }

    __shared__ float s_red[4][32][3];

    int hist = g_hist[t];
    int rayCount = (hist < CAP) ? hist : CAP;

    // load this warp's 4 mask words (one uniform LDG.128), then zero for replay
    uint4 mw = ((const uint4*)g_mask)[t * 4 + warp];
    if (lane == 0) ((uint4*)g_mask)[t * 4 + warp] = make_uint4(0, 0, 0, 0);
    if (tid == 0) g_hist[t] = 0;

    if (rayCount == 0) return;   // block-uniform; masks already zeroed

    int bbase = t * CAP;
    for (int r0 = 0; r0 < rayCount; r0 += 32) {
        if (r0 > 0) __syncthreads();       // protect s_red across batches
        int myIdx = r0 + lane;
        bool active = myIdx < rayCount;
        int ray = 0;
        float px = 0.0f, py = 0.0f;
        if (active) {
            float2 xy = g_bxy[bbase + myIdx];   // same addrs in all 4 warps (L1)
            ray = g_bid[bbase + myIdx];
            px = xy.x - (WPIX * 0.5f);
            py = xy.y - (HPIX * 0.5f);
        }
        float sumR = 0.0f, sumG = 0.0f, sumB = 0.0f;

#pragma unroll
        for (int k = 0; k < 4; ++k) {
            unsigned word = (k == 0) ? mw.x : (k == 1) ? mw.y : (k == 2) ? mw.z : mw.w;
            int nb = (warp * 4 + k) * 32;
            while (word) {                       // warp-uniform bit walk
                int b = __ffs(word) - 1;
                word &= word - 1;
                int n = nb + b;
                splat_accum(px, py, g_ga[n], &g_gb[n], &g_sh[n * 7],
                            sumR, sumG, sumB);
            }
        }

        s_red[warp][lane][0] = sumR;
        s_red[warp][lane][1] = sumG;
        s_red[warp][lane][2] = sumB;
        __syncthreads();

        if (warp == 0 && active) {
            // fixed order: ((w0 + w1) + w2) + w3  -> deterministic
            float r = ((s_red[0][lane][0] + s_red[1][lane][0]) + s_red[2][lane][0]) + s_red[3][lane][0];
            float g = ((s_red[0][lane][1] + s_red[1][lane][1]) + s_red[2][lane][1]) + s_red[3][lane][1];
            float b = ((s_red[0][lane][2] + s_red[1][lane][2]) + s_red[2][lane][2]) + s_red[3][lane][2];
            out[3 * ray + 0] = r;
            out[3 * ray + 1] = g;
            out[3 * ray + 2] = b;
        }
    }
}

extern "C" void kernel_launch(void* const* d_in, const int* in_sizes, int n_in,
                              void* d_out, int out_size) {
    // metadata order: x, rgbsh, opacity, mu, scale, angle
    const float* x       = (const float*)d_in[0];
    const float* rgbsh   = (const float*)d_in[1];
    const float* opacity = (const float*)d_in[2];
    const float* mu      = (const float*)d_in[3];
    const float* scale   = (const float*)d_in[4];
    const float* angle   = (const float*)d_in[5];
    float* out = (float*)d_out;

    int B = in_sizes[0] / 2;
    int N = in_sizes[2];
    if (N > MAX_N) N = MAX_N;

    // binning: 2 rays per thread (one float4), 512 rays per 256-thread block
    int binBlocks = (B + 511) / 512;
    prep_kernel<<<binBlocks + PRE_BLOCKS, 256>>>(x, rgbsh, opacity, mu, scale, angle, B, N, binBlocks);

    splat_kernel<<<NUM_TILES + 1, 128>>>(out, B, N);
}

// round 14
// speedup vs baseline: 1.6911x; 1.1533x over previous
#include <cuda_runtime.h>
#include <cuda_bf16.h>

// Problem constants (match reference)
#define WPIX 512.0f
#define HPIX 512.0f
#define S_MIN (1.0f / 30.0f)
#define S_MAX (1.0f / 0.75f)
#define MU_BORDER 1.05f
#define PI_APPROX 3.1416f

#define MAX_N 512
#define MAX_B 65536
#define TILE_PX 16.0f
#define TILES_X 32
#define TILES_Y 32
#define NUM_TILES (TILES_X * TILES_Y)
#define PRE_BLOCKS 16
#define G_PER_BLOCK 32        // 512 / 16
#define CAP 256               // bucket capacity per tile (mean load = 32)
#define MASK_WORDS 16         // 512 bits per tile

// ---- per-gaussian precomputed data ----
__device__ float4 g_ga[MAX_N];          // (gmx, gmy, Sx, Sy), centered px coords
__device__ float4 g_gb[MAX_N];          // (cos a, sin a, sigmoid(op), 0)
__device__ float4 g_sh[MAX_N * 7];      // repacked 27 SH coeffs + pad

// ---- tile -> gaussian candidacy bitmasks (atomicOr = order-independent) ----
__device__ unsigned g_mask[NUM_TILES * MASK_WORDS];  // .bss zero; splat re-zeroes

// ---- direct ray buckets ----
__device__ int    g_hist[NUM_TILES];    // .bss zero; re-zeroed by splat each call
__device__ float2 g_bxy[NUM_TILES * CAP];
__device__ int    g_bid[NUM_TILES * CAP];
// overflow (correctness fallback; empty for benchmark inputs)
__device__ int    g_ovf_cnt;
__device__ float2 g_ovf_xy[MAX_B];
__device__ int    g_ovf_id[MAX_B];

__device__ __forceinline__ int tile_of(float xr, float yr) {
    int tx = min(TILES_X - 1, max(0, (int)(xr * (1.0f / TILE_PX))));
    int ty = min(TILES_Y - 1, max(0, (int)(yr * (1.0f / TILE_PX))));
    return ty * TILES_X + tx;
}

// Branchless per-pair accumulate. All loads issued by the CALLER (unconditional);
// for d2 >= 25 the weight is exactly 0 and fmaf(0, r, sum) == sum bitwise,
// so results are identical to the branchy skip.
__device__ __forceinline__ void splat_accum_bl(
    float px, float py, float4 ga, float4 gb,
    float4 q0, float4 q1, float4 q2, float4 q3,
    float4 q4, float4 q5, float4 q6,
    float& sumR, float& sumG, float& sumB)
{
    float vx = px - ga.x;
    float vy = py - ga.y;
    float svx = vx * ga.z;
    float svy = vy * ga.w;
    float d2 = fmaf(svx, svx, svy * svy);

    float c = gb.x, sa = gb.y;
    float w = (d2 < 25.0f) ? __expf(-d2) * gb.z : 0.0f;

    float rvx = c * vx - sa * vy;
    float rvy = fmaf(sa, vx, c * vy);
    float rn = rsqrtf(fmaf(rvx, rvx, fmaf(rvy, rvy, 1e-20f)));
    float s1 = rvx * rn;   // sin(theta)
    float c1 = rvy * rn;   // cos(theta)
    float s2 = 2.0f * s1 * c1;
    float c2 = fmaf(c1, c1, -s1 * s1);
    float s3 = fmaf(s1, c2, c1 * s2);
    float c3 = fmaf(c1, c2, -s1 * s2);
    float s4 = 2.0f * s2 * c2;
    float c4 = fmaf(c2, c2, -s2 * s2);

    float aR = q0.x;
    aR = fmaf(s1, q0.w, aR); aR = fmaf(c1, q1.z, aR);
    aR = fmaf(s2, q2.y, aR); aR = fmaf(c2, q3.x, aR);
    aR = fmaf(s3, q3.w, aR); aR = fmaf(c3, q4.z, aR);
    aR = fmaf(s4, q5.y, aR); aR = fmaf(c4, q6.x, aR);
    float aG = q0.y;
    aG = fmaf(s1, q1.x, aG); aG = fmaf(c1, q1.w, aG);
    aG = fmaf(s2, q2.z, aG); aG = fmaf(c2, q3.y, aG);
    aG = fmaf(s3, q4.x, aG); aG = fmaf(c3, q4.w, aG);
    aG = fmaf(s4, q5.z, aG); aG = fmaf(c4, q6.y, aG);
    float aB = q0.z;
    aB = fmaf(s1, q1.y, aB); aB = fmaf(c1, q2.x, aB);
    aB = fmaf(s2, q2.w, aB); aB = fmaf(c2, q3.z, aB);
    aB = fmaf(s3, q4.y, aB); aB = fmaf(c3, q5.x, aB);
    aB = fmaf(s4, q5.w, aB); aB = fmaf(c4, q6.z, aB);

    float rR = __fdividef(1.0f, 1.0f + __expf(-aR));
    float rG = __fdividef(1.0f, 1.0f + __expf(-aG));
    float rB = __fdividef(1.0f, 1.0f + __expf(-aB));
    sumR = fmaf(w, rR, sumR);
    sumG = fmaf(w, rG, sumG);
    sumB = fmaf(w, rB, sumB);
}

// ============================================================================
// K1: blocks [0, binBlocks): ray binning -> direct bucket scatter (2 rays/thr)
//     blocks [binBlocks, binBlocks+PRE_BLOCKS): per-gaussian precompute +
//       bitmask scatter (atomicOr, order-independent -> deterministic)
// 256 threads/block.
// ============================================================================
__global__ __launch_bounds__(256)
void prep_kernel(const float* __restrict__ x,
                 const float* __restrict__ rgbsh,
                 const float* __restrict__ opacity,
                 const float* __restrict__ mu,
                 const float* __restrict__ scale,
                 const float* __restrict__ angle,
                 int B, int N, int binBlocks) {
    int bid = blockIdx.x;
    int tid = threadIdx.x;

    if (bid < binBlocks) {
        const float4* x4 = (const float4*)x;
        int f = bid * 256 + tid;            // float4 index = rays 2f, 2f+1
        if (2 * f < B) {
            float4 v = x4[f];
#pragma unroll
            for (int j = 0; j < 2; ++j) {
                int r = 2 * f + j;
                if (r < B) {
                    float xr = (j == 0) ? v.x : v.z;
                    float yr = (j == 0) ? v.y : v.w;
                    int t = tile_of(xr, yr);
                    int pos = atomicAdd(&g_hist[t], 1);
                    if (pos < CAP) {
                        g_bxy[t * CAP + pos] = make_float2(xr, yr);
                        g_bid[t * CAP + pos] = r;
                    } else {
                        int o = atomicAdd(&g_ovf_cnt, 1);
                        g_ovf_xy[o] = make_float2(xr, yr);
                        g_ovf_id[o] = r;
                    }
                }
            }
        }
    } else {
        int g0 = (bid - binBlocks) * G_PER_BLOCK;
        if (tid < G_PER_BLOCK) {
            int n = g0 + tid;
            if (n < N) {
                float gmx = tanhf(mu[2 * n + 0]) * (MU_BORDER * WPIX * 0.5f);
                float gmy = tanhf(mu[2 * n + 1]) * (MU_BORDER * HPIX * 0.5f);
                float sx = fminf(fmaxf(scale[2 * n + 0], 0.0f), 1.0f) * (S_MAX - S_MIN) + S_MIN;
                float sy = fminf(fmaxf(scale[2 * n + 1], 0.0f), 1.0f) * (S_MAX - S_MIN) + S_MIN;
                g_ga[n] = make_float4(gmx, gmy, sx, sy);

                float alpha = tanhf(angle[n]) * PI_APPROX;
                float c, s;
                sincosf(alpha, &s, &c);
                float op = 1.0f / (1.0f + expf(-opacity[n]));
                g_gb[n] = make_float4(c, s, op, 0.0f);

                // conservative bbox of valid ellipse, raw pixel coords
                float hx = __fdividef(5.0f, sx) + 0.05f;
                float hy = __fdividef(5.0f, sy) + 0.05f;
                float cx = gmx + WPIX * 0.5f;
                float cy = gmy + HPIX * 0.5f;
                float xmin = cx - hx, xmax = cx + hx;
                float ymin = cy - hy, ymax = cy + hy;

                // tile rect overlapping bbox (conservative)
                int tx0 = max(0, (int)ceilf(xmin * (1.0f / TILE_PX)) - 1);
                int tx1 = min(TILES_X - 1, (int)floorf(xmax * (1.0f / TILE_PX)));
                int ty0 = max(0, (int)ceilf(ymin * (1.0f / TILE_PX)) - 1);
                int ty1 = min(TILES_Y - 1, (int)floorf(ymax * (1.0f / TILE_PX)));

                unsigned bit = 1u << (n & 31);
                int word = n >> 5;
                for (int ty = ty0; ty <= ty1; ++ty)
                    for (int tx = tx0; tx <= tx1; ++tx)
                        atomicOr(&g_mask[(ty * TILES_X + tx) * MASK_WORDS + word], bit);
            }
        } else {
            // SH repack: 224 tasks = 32 gaussians x 7 slots
            int task = tid - G_PER_BLOCK;
            int sl = task / 7;
            int j = task - sl * 7;
            int n = g0 + sl;
            if (n < N) {
                int c0 = 4 * j;
                float v0 = rgbsh[n * 27 + c0];
                float v1 = (c0 + 1 < 27) ? rgbsh[n * 27 + c0 + 1] : 0.0f;
                float v2 = (c0 + 2 < 27) ? rgbsh[n * 27 + c0 + 2] : 0.0f;
                float v3 = (c0 + 3 < 27) ? rgbsh[n * 27 + c0 + 3] : 0.0f;
                g_sh[n * 7 + j] = make_float4(v0, v1, v2, v3);
            }
        }
    }
}

// ============================================================================
// K2: splat — 128 threads per tile; warp w owns mask words 4w..4w+3.
// Branchless candidate loop with unconditional parallel loads.
// Block NUM_TILES: overflow fallback (empty in practice).
// ============================================================================
__global__ __launch_bounds__(128)
void splat_kernel(float* __restrict__ out, int B, int N) {
    int t = blockIdx.x;
    int tid = threadIdx.x;
    int warp = tid >> 5;
    int lane = tid & 31;

    if (t == NUM_TILES) {
        int nOvf = g_ovf_cnt;
        __syncthreads();
        if (tid == 0) g_ovf_cnt = 0;
        int cap = (nOvf < MAX_B) ? nOvf : MAX_B;
        for (int i = tid; i < cap; i += 128) {
            float2 xy = g_ovf_xy[i];
            int ray = g_ovf_id[i];
            float px = xy.x - (WPIX * 0.5f);
            float py = xy.y - (HPIX * 0.5f);
            float sumR = 0.0f, sumG = 0.0f, sumB = 0.0f;
            for (int n = 0; n < N; ++n) {
                const float4* sh = &g_sh[n * 7];
                splat_accum_bl(px, py, g_ga[n], g_gb[n],
                               sh[0], sh[1], sh[2], sh[3], sh[4], sh[5], sh[6],
                               sumR, sumG, sumB);
            }
            out[3 * ray + 0] = sumR;
            out[3 * ray + 1] = sumG;
            out[3 * ray + 2] = sumB;
        }
        return;
    }

    __shared__ float s_red[4][32][3];

    // ---- prologue: issue all independent loads before any dependent branch ----
    int hist = g_hist[t];
    uint4 mw = ((const uint4*)g_mask)[t * 4 + warp];
    int bbase = t * CAP;
    // first-batch bucket entries, unconditional (arrays fully sized -> safe)
    float2 xy0 = g_bxy[bbase + lane];
    int id0 = g_bid[bbase + lane];

    if (lane == 0) ((uint4*)g_mask)[t * 4 + warp] = make_uint4(0, 0, 0, 0);
    if (tid == 0) g_hist[t] = 0;

    int rayCount = (hist < CAP) ? hist : CAP;
    if (rayCount == 0) return;   // masks/hist already zeroed

    for (int r0 = 0; r0 < rayCount; r0 += 32) {
        if (r0 > 0) __syncthreads();       // protect s_red across batches
        int myIdx = r0 + lane;
        bool active = myIdx < rayCount;
        float2 xy;
        int ray;
        if (r0 == 0) { xy = xy0; ray = id0; }
        else {
            int ci = (myIdx < CAP) ? myIdx : (CAP - 1);
            xy = g_bxy[bbase + ci];
            ray = g_bid[bbase + ci];
        }
        float px = xy.x - (WPIX * 0.5f);
        float py = xy.y - (HPIX * 0.5f);
        float sumR = 0.0f, sumG = 0.0f, sumB = 0.0f;

#pragma unroll
        for (int k = 0; k < 4; ++k) {
            unsigned word = (k == 0) ? mw.x : (k == 1) ? mw.y : (k == 2) ? mw.z : mw.w;
            int nb = (warp * 4 + k) * 32;
            while (word) {                       // warp-uniform bit walk
                int b = __ffs(word) - 1;
                word &= word - 1;
                int n = nb + b;
                // all 9 loads unconditional & independent -> single L2 round,
                // overlaps with previous iteration's math
                float4 ga = g_ga[n];
                float4 gb = g_gb[n];
                const float4* shp = &g_sh[n * 7];
                float4 q0 = shp[0], q1 = shp[1], q2 = shp[2], q3 = shp[3];
                float4 q4 = shp[4], q5 = shp[5], q6 = shp[6];
                splat_accum_bl(px, py, ga, gb, q0, q1, q2, q3, q4, q5, q6,
                               sumR, sumG, sumB);
            }
        }

        s_red[warp][lane][0] = sumR;
        s_red[warp][lane][1] = sumG;
        s_red[warp][lane][2] = sumB;
        __syncthreads();

        if (warp == 0 && active) {
            // fixed order: ((w0 + w1) + w2) + w3  -> deterministic
            float r = ((s_red[0][lane][0] + s_red[1][lane][0]) + s_red[2][lane][0]) + s_red[3][lane][0];
            float g = ((s_red[0][lane][1] + s_red[1][lane][1]) + s_red[2][lane][1]) + s_red[3][lane][1];
            float b = ((s_red[0][lane][2] + s_red[1][lane][2]) + s_red[2][lane][2]) + s_red[3][lane][2];
            out[3 * ray + 0] = r;
            out[3 * ray + 1] = g;
            out[3 * ray + 2] = b;
        }
    }
}

extern "C" void kernel_launch(void* const* d_in, const int* in_sizes, int n_in,
                              void* d_out, int out_size) {
    // metadata order: x, rgbsh, opacity, mu, scale, angle
    const float* x       = (const float*)d_in[0];
    const float* rgbsh   = (const float*)d_in[1];
    const float* opacity = (const float*)d_in[2];
    const float* mu      = (const float*)d_in[3];
    const float* scale   = (const float*)d_in[4];
    const float* angle   = (const float*)d_in[5];
    float* out = (float*)d_out;

    int B = in_sizes[0] / 2;
    int N = in_sizes[2];
    if (N > MAX_N) N = MAX_N;

    // binning: 2 rays per thread (one float4), 512 rays per 256-thread block
    int binBlocks = (B + 511) / 512;
    prep_kernel<<<binBlocks + PRE_BLOCKS, 256>>>(x, rgbsh, opacity, mu, scale, angle, B, N, binBlocks);

    splat_kernel<<<NUM_TILES + 1, 128>>>(out, B, N);
}